// round 16
// baseline (speedup 1.0000x reference)
#include <cuda_runtime.h>
#include <cstdint>
#include <cstddef>

// Problem constants
#define BB 128
#define TT 20
#define VV 10000
#define EE 512
#define HH 1024
#define FF 196
#define DD 512

// ---------------------------------------------------------------------------
// Device scratch
// ---------------------------------------------------------------------------
__device__ float g_a_feat[(size_t)BB * FF * DD];
__device__ float g_x_emb[(size_t)BB * TT * EE];
__device__ float g_gemb[(size_t)BB * TT * 4 * HH];
__device__ float g_hall[(size_t)BB * TT * HH];
__device__ float g_h[BB * HH];
__device__ float g_c[BB * HH];
__device__ float g_z[BB * DD];
__device__ float g_z0[BB * DD];
__device__ float g_hg[4 * BB * 4608];         // split-K=4 partials: [W_hh|W_h2a]
__device__ float g_zg[2 * BB * 4 * HH];       // split-K=2 z-gates partials

__device__ __forceinline__ uint32_t f2tf32(float x) {
    uint32_t r;
    asm("cvt.rna.tf32.f32 %0, %1;" : "=r"(r) : "f"(x));
    return r;
}

__device__ __forceinline__ void mma_tf32(float c[4], const uint32_t a[4],
                                         const uint32_t b[2]) {
    asm volatile(
        "mma.sync.aligned.m16n8k8.row.col.f32.tf32.tf32.f32 "
        "{%0,%1,%2,%3}, {%4,%5,%6,%7}, {%8,%9}, {%0,%1,%2,%3};"
        : "+f"(c[0]), "+f"(c[1]), "+f"(c[2]), "+f"(c[3])
        : "r"(a[0]), "r"(a[1]), "r"(a[2]), "r"(a[3]), "r"(b[0]), "r"(b[1]));
}

// ---------------------------------------------------------------------------
// Tensor-core (mma.sync tf32) GEMM: C[M,N] = A[M,K] * B[N,K]^T
// CTA tile 128x128, BK=16, double-buffered static smem, 8 warps of 64x32.
//   MODE 0: C = acc + bias[n] (+ bias2[n]).  M%128==0, N%128==0.
//   MODE 5: split-K partial: kofs = zi*K; raw partial -> C + zi*M*ldc.
//   MODE 6: fc chunk over 10 steps: row gm -> b = gm/10, t = tstep + gm%10;
//           A row = hall + (b*TT+t)*HH; C row = out + (b*TT+t)*VV;
//           v = lengths[b] >= t ? acc + bias : 0. N-bounds checked.
//   MODE 7: h-GEMM: A = h (ld 1024); B row gn<4096 ? W_hh[gn] : W_h2a[gn-4096]
//           (both ld 1024); split-K kofs = zi*K; raw -> C + zi*M*ldc.
// ---------------------------------------------------------------------------
#define SROW 20

template<int MODE>
__global__ void __launch_bounds__(256, 2)
mma_gemm(const float* __restrict__ A, int lda,
         const float* __restrict__ Bm, int ldb,
         const float* __restrict__ B2,
         const float* __restrict__ bias, const float* __restrict__ bias2,
         float* __restrict__ C, int ldc,
         int M, int N, int K,
         const int* __restrict__ lengths, int tstep)
{
    __shared__ __align__(16) float As[2][128 * SROW];
    __shared__ __align__(16) float Bs[2][128 * SROW];

    const int tid = threadIdx.x;
    const int wid = tid >> 5;
    const int lane = tid & 31;
    const int g = lane >> 2;
    const int l = lane & 3;
    const int wm = (wid >> 2) * 64;
    const int wn = (wid & 3) * 32;
    const long m0 = (long)blockIdx.x * 128;
    const long n0 = (long)blockIdx.y * 128;
    const int zi = blockIdx.z;
    const int kofs = (MODE == 5 || MODE == 7) ? zi * K : 0;

    float acc[4][4][4];
#pragma unroll
    for (int i = 0; i < 4; i++)
#pragma unroll
        for (int j = 0; j < 4; j++)
#pragma unroll
            for (int k = 0; k < 4; k++) acc[i][j][k] = 0.f;

    float4 va[2], vb[2];
    auto ldgA = [&](int k0) {
#pragma unroll
        for (int i = 0; i < 2; i++) {
            int lin = tid + i * 256;
            int r = lin >> 2, kq = lin & 3;
            int gk = k0 + kq * 4 + kofs;
            if (MODE == 6) {
                long gm = m0 + r;
                int b = (int)(gm / 10);
                int tt = tstep + (int)(gm % 10);
                va[i] = *(const float4*)(A + ((size_t)b * TT + tt) * HH + gk);
            } else {
                va[i] = *(const float4*)(A + (size_t)(m0 + r) * lda + gk);
            }
        }
    };
    auto ldgB = [&](int k0) {
#pragma unroll
        for (int i = 0; i < 2; i++) {
            int lin = tid + i * 256;
            int r = lin >> 2, kq = lin & 3;
            long gn = n0 + r;
            int gk = k0 + kq * 4 + kofs;
            if (MODE == 7) {
                const float* p = (gn < 4096)
                    ? (Bm + (size_t)gn * 1024 + gk)
                    : (B2 + (size_t)(gn - 4096) * 1024 + gk);
                vb[i] = *(const float4*)p;
            } else if (MODE == 6) {
                vb[i] = (gn < N) ? *(const float4*)(Bm + (size_t)gn * ldb + gk)
                                 : make_float4(0.f, 0.f, 0.f, 0.f);
            } else {
                vb[i] = *(const float4*)(Bm + (size_t)gn * ldb + gk);
            }
        }
    };
    auto stsAB = [&](int buf) {
#pragma unroll
        for (int i = 0; i < 2; i++) {
            int lin = tid + i * 256;
            int r = lin >> 2, kq = lin & 3;
            float4 ta, tb;
            ta.x = __uint_as_float(f2tf32(va[i].x));
            ta.y = __uint_as_float(f2tf32(va[i].y));
            ta.z = __uint_as_float(f2tf32(va[i].z));
            ta.w = __uint_as_float(f2tf32(va[i].w));
            tb.x = __uint_as_float(f2tf32(vb[i].x));
            tb.y = __uint_as_float(f2tf32(vb[i].y));
            tb.z = __uint_as_float(f2tf32(vb[i].z));
            tb.w = __uint_as_float(f2tf32(vb[i].w));
            *(float4*)&As[buf][r * SROW + kq * 4] = ta;
            *(float4*)&Bs[buf][r * SROW + kq * 4] = tb;
        }
    };

    const int nt_tiles = K >> 4;

    ldgA(0); ldgB(0);
    stsAB(0);
    __syncthreads();

    for (int kt = 0; kt < nt_tiles; kt++) {
        const int buf = kt & 1;
        const bool has_next = (kt + 1) < nt_tiles;
        if (has_next) { ldgA((kt + 1) * 16); ldgB((kt + 1) * 16); }

        const float* As_ = As[buf];
        const float* Bs_ = Bs[buf];
#pragma unroll
        for (int k8 = 0; k8 < 2; k8++) {
            const int kc = k8 * 8;
            uint32_t af[4][4];
#pragma unroll
            for (int mt = 0; mt < 4; mt++) {
                const float* p = As_ + (wm + mt * 16 + g) * SROW + kc + l;
                af[mt][0] = __float_as_uint(p[0]);
                af[mt][1] = __float_as_uint(p[8 * SROW]);
                af[mt][2] = __float_as_uint(p[4]);
                af[mt][3] = __float_as_uint(p[8 * SROW + 4]);
            }
            uint32_t bfr[4][2];
#pragma unroll
            for (int ntile = 0; ntile < 4; ntile++) {
                const float* q = Bs_ + (wn + ntile * 8 + g) * SROW + kc + l;
                bfr[ntile][0] = __float_as_uint(q[0]);
                bfr[ntile][1] = __float_as_uint(q[4]);
            }
#pragma unroll
            for (int mt = 0; mt < 4; mt++)
#pragma unroll
                for (int ntile = 0; ntile < 4; ntile++)
                    mma_tf32(acc[mt][ntile], af[mt], bfr[ntile]);
        }

        if (has_next) {
            stsAB(buf ^ 1);
            __syncthreads();
        }
    }

    // ---- epilogue ----
    float* Cp = C;
    if (MODE == 5 || MODE == 7) Cp = C + (size_t)zi * M * ldc;

#pragma unroll
    for (int mt = 0; mt < 4; mt++) {
        const int r0l = wm + mt * 16 + g;
        const int r1l = r0l + 8;
        long gm0 = m0 + r0l, gm1 = m0 + r1l;
        float *crow0, *crow1;
        bool msk0 = true, msk1 = true;
        if (MODE == 6) {
            int b0 = (int)(gm0 / 10), t0 = tstep + (int)(gm0 % 10);
            int b1 = (int)(gm1 / 10), t1 = tstep + (int)(gm1 % 10);
            crow0 = C + ((size_t)b0 * TT + t0) * ldc;
            crow1 = C + ((size_t)b1 * TT + t1) * ldc;
            msk0 = (lengths[b0] >= t0);
            msk1 = (lengths[b1] >= t1);
        } else {
            crow0 = Cp + (size_t)gm0 * ldc;
            crow1 = Cp + (size_t)gm1 * ldc;
        }
#pragma unroll
        for (int ntile = 0; ntile < 4; ntile++) {
            const int cn = wn + ntile * 8 + 2 * l;
            long gn = n0 + cn;
            if (MODE == 6 && gn >= N) continue;
            float2 v0 = make_float2(acc[mt][ntile][0], acc[mt][ntile][1]);
            float2 v1 = make_float2(acc[mt][ntile][2], acc[mt][ntile][3]);
            if (MODE == 0) {
                float bx = bias[gn], by = bias[gn + 1];
                if (bias2) { bx += bias2[gn]; by += bias2[gn + 1]; }
                v0.x += bx; v0.y += by; v1.x += bx; v1.y += by;
            } else if (MODE == 6) {
                float bx = bias[gn], by = bias[gn + 1];
                v0.x = msk0 ? (v0.x + bx) : 0.f;
                v0.y = msk0 ? (v0.y + by) : 0.f;
                v1.x = msk1 ? (v1.x + bx) : 0.f;
                v1.y = msk1 ? (v1.y + by) : 0.f;
            }
            *(float2*)(crow0 + gn) = v0;
            *(float2*)(crow1 + gn) = v1;
        }
    }
}

// ---------------------------------------------------------------------------
// Support kernels
// ---------------------------------------------------------------------------
__global__ void gather_kernel(const int* __restrict__ cap,
                              const float* __restrict__ emb,
                              float* __restrict__ xe)
{
    int r = blockIdx.x;
    int i = threadIdx.x;
    const float4* src = (const float4*)(emb + (size_t)cap[r] * EE);
    ((float4*)(xe + (size_t)r * EE))[i] = src[i];
}

// ---------------------------------------------------------------------------
// Fused attention, 512 threads. a_h = b_h2a + sum of 4 hg partials (cols 4096+).
// ---------------------------------------------------------------------------
__global__ void __launch_bounds__(512)
attn_fused(const float* __restrict__ a_feat,
           const float* __restrict__ hg,
           const float* __restrict__ b_h2a,
           const float* __restrict__ w_a,
           const float* __restrict__ b_a,
           const float* __restrict__ feature,
           float* __restrict__ z)
{
    int b = blockIdx.x;
    int tid = threadIdx.x;
    int warp = tid >> 5, lane = tid & 31;
    __shared__ __align__(16) float s_ah[DD];
    __shared__ __align__(16) float s_w[DD];
    __shared__ float s_sc[FF];
    __shared__ __align__(16) float s_zp[4][DD];
    __shared__ float red[16];
    __shared__ float bmax, bsum;

    const size_t HGS = (size_t)BB * 4608;
    for (int i = tid; i < DD / 4; i += 512) {
        float4 v = ((const float4*)b_h2a)[i];
#pragma unroll
        for (int zp = 0; zp < 4; zp++) {
            float4 p = *(const float4*)(hg + (size_t)zp * HGS
                                        + (size_t)b * 4608 + 4096 + i * 4);
            v.x += p.x; v.y += p.y; v.z += p.z; v.w += p.w;
        }
        ((float4*)s_ah)[i] = v;
        ((float4*)s_w)[i]  = ((const float4*)w_a)[i];
    }
    __syncthreads();

    float ba = b_a[0];
    for (int f = warp; f < FF; f += 16) {
        const float4* af = (const float4*)(a_feat + ((size_t)b * FF + f) * DD);
        float s = 0.f;
#pragma unroll 4
        for (int k = lane; k < DD / 4; k += 32) {
            float4 a = af[k];
            float4 h4 = ((const float4*)s_ah)[k];
            float4 w4 = ((const float4*)s_w)[k];
            s += fmaxf(a.x + h4.x, 0.f) * w4.x
               + fmaxf(a.y + h4.y, 0.f) * w4.y
               + fmaxf(a.z + h4.z, 0.f) * w4.z
               + fmaxf(a.w + h4.w, 0.f) * w4.w;
        }
#pragma unroll
        for (int o = 16; o; o >>= 1) s += __shfl_down_sync(0xffffffffu, s, o);
        if (lane == 0) s_sc[f] = s + ba;
    }
    __syncthreads();

    float v = (tid < FF) ? s_sc[tid] : -3.0e38f;
    float m = v;
#pragma unroll
    for (int o = 16; o; o >>= 1) m = fmaxf(m, __shfl_xor_sync(0xffffffffu, m, o));
    if (lane == 0) red[warp] = m;
    __syncthreads();
    if (tid == 0) {
        float x = red[0];
        for (int w = 1; w < 16; w++) x = fmaxf(x, red[w]);
        bmax = x;
    }
    __syncthreads();
    float e = (tid < FF) ? expf(v - bmax) : 0.f;
    float s = e;
#pragma unroll
    for (int o = 16; o; o >>= 1) s += __shfl_xor_sync(0xffffffffu, s, o);
    if (lane == 0) red[warp] = s;
    __syncthreads();
    if (tid == 0) {
        float x = 0.f;
        for (int w = 0; w < 16; w++) x += red[w];
        bsum = x;
    }
    __syncthreads();
    if (tid < FF) s_sc[tid] = e / bsum;
    __syncthreads();

    {
        int quarter = tid >> 7;
        int dt = (tid & 127) * 4;
        int f0 = quarter * 49;
        int f1 = f0 + 49;
        const float4* fp = (const float4*)(feature + (size_t)b * FF * DD) + (dt >> 2);
        float a0 = 0.f, a1 = 0.f, a2 = 0.f, a3 = 0.f;
        for (int f = f0; f < f1; f++) {
            float4 q = fp[(size_t)f * (DD / 4)];
            float al = s_sc[f];
            a0 += al * q.x; a1 += al * q.y;
            a2 += al * q.z; a3 += al * q.w;
        }
        *(float4*)&s_zp[quarter][dt] = make_float4(a0, a1, a2, a3);
    }
    __syncthreads();
    if (tid < 128) {
        int dt = tid * 4;
        float4 u0 = *(const float4*)&s_zp[0][dt];
        float4 u1 = *(const float4*)&s_zp[1][dt];
        float4 u2 = *(const float4*)&s_zp[2][dt];
        float4 u3 = *(const float4*)&s_zp[3][dt];
        u0.x += u1.x + u2.x + u3.x;
        u0.y += u1.y + u2.y + u3.y;
        u0.z += u1.z + u2.z + u3.z;
        u0.w += u1.w + u2.w + u3.w;
        *(float4*)(z + (size_t)b * DD + dt) = u0;
    }
}

__global__ void zmean_kernel(const float* __restrict__ feature,
                             float* __restrict__ z)
{
    int b = blockIdx.x;
    int d = blockIdx.y * 128 + threadIdx.x;
    const float* fp = feature + (size_t)b * FF * DD + d;
    float s0 = 0.f, s1 = 0.f, s2 = 0.f, s3 = 0.f;
    for (int f = 0; f < FF; f += 4) {
        s0 += fp[(size_t)(f + 0) * DD];
        s1 += fp[(size_t)(f + 1) * DD];
        s2 += fp[(size_t)(f + 2) * DD];
        s3 += fp[(size_t)(f + 3) * DD];
    }
    z[b * DD + d] = ((s0 + s1) + (s2 + s3)) * (1.0f / FF);
}

__device__ __forceinline__ float sigmoidf_(float x) { return 1.f / (1.f + expf(-x)); }

// LSTM pointwise, float4-vectorized (4 hh per thread):
// gates = sum(2 zg partials) + sum(4 hg partials, cols 0..4096) + gemb.
__global__ void __launch_bounds__(256)
lstm_kernel(const float* __restrict__ zg,
            const float* __restrict__ hg,
            const float* __restrict__ gemb,
            const int* __restrict__ lengths, int t,
            float* __restrict__ h, float* __restrict__ c,
            float* __restrict__ hall)
{
    int idx = blockIdx.x * blockDim.x + threadIdx.x;   // BB*HH/4 threads
    int b = idx >> 8;                                  // HH/4 = 256
    int hh = (idx & 255) * 4;
    const size_t HGS = (size_t)BB * 4608;
    const size_t ZGS = (size_t)BB * 4096;
    const float* zgb = zg + (size_t)b * 4096;
    const float* hgb = hg + (size_t)b * 4608;
    const float* ge  = gemb + ((size_t)b * TT + t) * 4 * HH;

    float4 gate[4];
#pragma unroll
    for (int g = 0; g < 4; g++) {
        int col = g * HH + hh;
        float4 v = *(const float4*)(ge + col);
        float4 q0 = *(const float4*)(zgb + col);
        float4 q1 = *(const float4*)(zgb + ZGS + col);
        v.x += q0.x + q1.x; v.y += q0.y + q1.y;
        v.z += q0.z + q1.z; v.w += q0.w + q1.w;
#pragma unroll
        for (int zp = 0; zp < 4; zp++) {
            float4 p = *(const float4*)(hgb + (size_t)zp * HGS + col);
            v.x += p.x; v.y += p.y; v.z += p.z; v.w += p.w;
        }
        gate[g] = v;
    }

    float4 cv = *(const float4*)(c + (size_t)b * HH + hh);
    float4 cn, hn;
    {
        float ii, ff, gg, oo;
        ii = sigmoidf_(gate[0].x); ff = sigmoidf_(gate[1].x);
        gg = tanhf(gate[2].x);     oo = sigmoidf_(gate[3].x);
        cn.x = ff * cv.x + ii * gg; hn.x = oo * tanhf(cn.x);
        ii = sigmoidf_(gate[0].y); ff = sigmoidf_(gate[1].y);
        gg = tanhf(gate[2].y);     oo = sigmoidf_(gate[3].y);
        cn.y = ff * cv.y + ii * gg; hn.y = oo * tanhf(cn.y);
        ii = sigmoidf_(gate[0].z); ff = sigmoidf_(gate[1].z);
        gg = tanhf(gate[2].z);     oo = sigmoidf_(gate[3].z);
        cn.z = ff * cv.z + ii * gg; hn.z = oo * tanhf(cn.z);
        ii = sigmoidf_(gate[0].w); ff = sigmoidf_(gate[1].w);
        gg = tanhf(gate[2].w);     oo = sigmoidf_(gate[3].w);
        cn.w = ff * cv.w + ii * gg; hn.w = oo * tanhf(cn.w);
    }

    *(float4*)(hall + ((size_t)b * TT + t) * HH + hh) = hn;
    if (lengths[b] >= t) {
        *(float4*)(h + (size_t)b * HH + hh) = hn;
        *(float4*)(c + (size_t)b * HH + hh) = cn;
    }
}

// ---------------------------------------------------------------------------
// Host orchestration
// ---------------------------------------------------------------------------
extern "C" void kernel_launch(void* const* d_in, const int* in_sizes, int n_in,
                              void* d_out, int out_size)
{
    const float* feature = (const float*)d_in[0];
    const int*   captions = (const int*)d_in[1];
    const int*   lengths = (const int*)d_in[2];
    const float* emb    = (const float*)d_in[3];
    const float* W_ih   = (const float*)d_in[4];
    const float* b_ih   = (const float*)d_in[5];
    const float* W_hh   = (const float*)d_in[6];
    const float* b_hh   = (const float*)d_in[7];
    const float* W_fc   = (const float*)d_in[8];
    const float* b_fc   = (const float*)d_in[9];
    const float* W_h2a  = (const float*)d_in[10];
    const float* b_h2a  = (const float*)d_in[11];
    const float* W_f2a  = (const float*)d_in[12];
    const float* b_f2a  = (const float*)d_in[13];
    const float* W_a2a  = (const float*)d_in[14];
    const float* b_a2a  = (const float*)d_in[15];
    float* out = (float*)d_out;

    float *a_feat, *x_e, *gemb, *hall, *h, *c, *z, *z0, *hg, *zg;
    cudaGetSymbolAddress((void**)&a_feat, g_a_feat);
    cudaGetSymbolAddress((void**)&x_e,    g_x_emb);
    cudaGetSymbolAddress((void**)&gemb,   g_gemb);
    cudaGetSymbolAddress((void**)&hall,   g_hall);
    cudaGetSymbolAddress((void**)&h,      g_h);
    cudaGetSymbolAddress((void**)&c,      g_c);
    cudaGetSymbolAddress((void**)&z,      g_z);
    cudaGetSymbolAddress((void**)&z0,     g_z0);
    cudaGetSymbolAddress((void**)&hg,     g_hg);
    cudaGetSymbolAddress((void**)&zg,     g_zg);

    static cudaStream_t s1 = nullptr;
    static cudaEvent_t evFork = nullptr, evA = nullptr, evG = nullptr;
    static cudaEvent_t evF1 = nullptr, evF2 = nullptr, evDone = nullptr;
    if (s1 == nullptr) {
        cudaStreamCreateWithFlags(&s1, cudaStreamNonBlocking);
        cudaEventCreateWithFlags(&evFork, cudaEventDisableTiming);
        cudaEventCreateWithFlags(&evA,    cudaEventDisableTiming);
        cudaEventCreateWithFlags(&evG,    cudaEventDisableTiming);
        cudaEventCreateWithFlags(&evF1,   cudaEventDisableTiming);
        cudaEventCreateWithFlags(&evF2,   cudaEventDisableTiming);
        cudaEventCreateWithFlags(&evDone, cudaEventDisableTiming);
    }

    cudaMemsetAsync(h,  0, (size_t)BB * HH * sizeof(float));
    cudaMemsetAsync(c,  0, (size_t)BB * HH * sizeof(float));
    cudaMemsetAsync(hg, 0, (size_t)4 * BB * 4608 * sizeof(float));
    gather_kernel<<<BB * TT, 128>>>(captions, emb, x_e);

    // Side stream: gemb GEMM (needed at lstm t=0), then a_feat (needed t=1)
    cudaEventRecord(evFork, 0);
    cudaStreamWaitEvent(s1, evFork, 0);
    mma_gemm<0><<<dim3(20, 32), 256, 0, s1>>>(
        x_e, EE, W_ih + DD, DD + EE, nullptr,
        b_ih, b_hh,
        gemb, 4 * HH, BB * TT, 4 * HH, EE, nullptr, 0);
    cudaEventRecord(evG, s1);
    mma_gemm<0><<<dim3(196, 4), 256, 0, s1>>>(
        feature, DD, W_f2a, DD, nullptr,
        b_f2a, nullptr,
        a_feat, DD, BB * FF, DD, DD, nullptr, 0);
    cudaEventRecord(evA, s1);

    zmean_kernel<<<dim3(BB, DD / 128), 128>>>(feature, z0);

    for (int t = 0; t < TT; t++) {
        if (t > 0) {
            // hg = h @ [W_hh | W_h2a]^T, split-K=4 partials [4][128][4608]
            mma_gemm<7><<<dim3(1, 36, 4), 256>>>(
                h, HH, W_hh, HH, W_h2a,
                nullptr, nullptr,
                hg, 4608, BB, 4608, 256, nullptr, 0);

            if (t == 1) cudaStreamWaitEvent(0, evA, 0);  // a_feat ready
            attn_fused<<<BB, 512>>>(a_feat, hg, b_h2a, W_a2a, b_a2a, feature, z);
        }

        // zg = z @ W_ih[:, :512]^T, split-K=2 partials [2][128][4096]
        mma_gemm<5><<<dim3(1, 32, 2), 256>>>(
            (t == 0) ? z0 : z, DD, W_ih, DD + EE, nullptr,
            nullptr, nullptr,
            zg, 4 * HH, BB, 4 * HH, 256, nullptr, 0);

        if (t == 0) cudaStreamWaitEvent(0, evG, 0);      // gemb ready
        lstm_kernel<<<(BB * HH / 4) / 256, 256>>>(zg, hg, gemb, lengths, t,
                                                  h, c, hall);

        if (t == 9) {
            // fc chunk A: steps 0..9 (hall rows final) on the side stream,
            // hidden under steps 10..19.
            cudaEventRecord(evF1, 0);
            cudaStreamWaitEvent(s1, evF1, 0);
            mma_gemm<6><<<dim3(10, 79), 256, 0, s1>>>(
                hall, 0, W_fc, HH, nullptr,
                b_fc, nullptr,
                out, VV, 1280, VV, HH, lengths, 0);
        }
    }

    // fc chunk B: steps 10..19 after the loop (side stream, then join).
    cudaEventRecord(evF2, 0);
    cudaStreamWaitEvent(s1, evF2, 0);
    mma_gemm<6><<<dim3(10, 79), 256, 0, s1>>>(
        hall, 0, W_fc, HH, nullptr,
        b_fc, nullptr,
        out, VV, 1280, VV, HH, lengths, 10);

    cudaEventRecord(evDone, s1);
    cudaStreamWaitEvent(0, evDone, 0);
}

// round 17
// speedup vs baseline: 1.2403x; 1.2403x over previous
#include <cuda_runtime.h>
#include <cstdint>
#include <cstddef>

// Problem constants
#define BB 128
#define TT 20
#define VV 10000
#define EE 512
#define HH 1024
#define FF 196
#define DD 512

// ---------------------------------------------------------------------------
// Device scratch
// ---------------------------------------------------------------------------
__device__ float g_a_feat[(size_t)BB * FF * DD];
__device__ float g_x_emb[(size_t)BB * TT * EE];
__device__ float g_gemb[(size_t)BB * TT * 4 * HH];
__device__ float g_hall[(size_t)BB * TT * HH];
__device__ float g_h[BB * HH];
__device__ float g_c[BB * HH];
__device__ float g_z[BB * DD];
__device__ float g_z0[BB * DD];
__device__ float g_hg[4 * BB * 4608];         // split-K=4 partials: [W_hh|W_h2a]
__device__ float g_zg[2 * BB * 4 * HH];       // split-K=2 z-gates partials
__device__ int   g_rowidx[BB * TT];
__device__ int   g_mact[1];

__device__ __forceinline__ uint32_t f2tf32(float x) {
    uint32_t r;
    asm("cvt.rna.tf32.f32 %0, %1;" : "=r"(r) : "f"(x));
    return r;
}

__device__ __forceinline__ void mma_tf32(float c[4], const uint32_t a[4],
                                         const uint32_t b[2]) {
    asm volatile(
        "mma.sync.aligned.m16n8k8.row.col.f32.tf32.tf32.f32 "
        "{%0,%1,%2,%3}, {%4,%5,%6,%7}, {%8,%9}, {%0,%1,%2,%3};"
        : "+f"(c[0]), "+f"(c[1]), "+f"(c[2]), "+f"(c[3])
        : "r"(a[0]), "r"(a[1]), "r"(a[2]), "r"(a[3]), "r"(b[0]), "r"(b[1]));
}

// ---------------------------------------------------------------------------
// Tensor-core (mma.sync tf32) GEMM: C[M,N] = A[M,K] * B[N,K]^T
// CTA tile 128x128, BK=16, double-buffered static smem, 8 warps of 64x32.
//   MODE 0: C = acc + bias[n] (+ bias2[n]).  M%128==0, N%128==0.
//   MODE 3: fc over compacted rows: A row = rowidx[m], m < *mact; N-bounds.
//   MODE 5: split-K partial: kofs = zi*K; raw partial -> C + zi*M*ldc.
//   MODE 7: h-GEMM: A = h (ld 1024); B row gn<4096 ? W_hh[gn] : W_h2a[gn-4096]
//           (both ld 1024); split-K kofs = zi*K; raw -> C + zi*M*ldc.
// ---------------------------------------------------------------------------
#define SROW 20

template<int MODE>
__global__ void __launch_bounds__(256, 2)
mma_gemm(const float* __restrict__ A, int lda,
         const float* __restrict__ Bm, int ldb,
         const float* __restrict__ B2,
         const float* __restrict__ bias, const float* __restrict__ bias2,
         float* __restrict__ C, int ldc,
         int M, int N, int K,
         const int* __restrict__ rowidx, const int* __restrict__ mact)
{
    __shared__ __align__(16) float As[2][128 * SROW];
    __shared__ __align__(16) float Bs[2][128 * SROW];
    __shared__ int sridx[128];

    const int tid = threadIdx.x;
    const int wid = tid >> 5;
    const int lane = tid & 31;
    const int g = lane >> 2;
    const int l = lane & 3;
    const int wm = (wid >> 2) * 64;
    const int wn = (wid & 3) * 32;
    const long m0 = (long)blockIdx.x * 128;
    const long n0 = (long)blockIdx.y * 128;
    const int zi = blockIdx.z;
    const int kofs = (MODE == 5 || MODE == 7) ? zi * K : 0;

    int Mact = M;
    if (MODE == 3) {
        Mact = *mact;
        if (m0 >= Mact) return;
        if (tid < 128) {
            long gm = m0 + tid;
            sridx[tid] = (gm < Mact) ? rowidx[gm] : -1;
        }
        __syncthreads();
    }

    float acc[4][4][4];
#pragma unroll
    for (int i = 0; i < 4; i++)
#pragma unroll
        for (int j = 0; j < 4; j++)
#pragma unroll
            for (int k = 0; k < 4; k++) acc[i][j][k] = 0.f;

    float4 va[2], vb[2];
    auto ldgA = [&](int k0) {
#pragma unroll
        for (int i = 0; i < 2; i++) {
            int lin = tid + i * 256;
            int r = lin >> 2, kq = lin & 3;
            int gk = k0 + kq * 4 + kofs;
            if (MODE == 3) {
                int ar = sridx[r];
                va[i] = (ar >= 0) ? *(const float4*)(A + (size_t)ar * lda + gk)
                                  : make_float4(0.f, 0.f, 0.f, 0.f);
            } else {
                va[i] = *(const float4*)(A + (size_t)(m0 + r) * lda + gk);
            }
        }
    };
    auto ldgB = [&](int k0) {
#pragma unroll
        for (int i = 0; i < 2; i++) {
            int lin = tid + i * 256;
            int r = lin >> 2, kq = lin & 3;
            long gn = n0 + r;
            int gk = k0 + kq * 4 + kofs;
            if (MODE == 7) {
                const float* p = (gn < 4096)
                    ? (Bm + (size_t)gn * 1024 + gk)
                    : (B2 + (size_t)(gn - 4096) * 1024 + gk);
                vb[i] = *(const float4*)p;
            } else if (MODE == 3) {
                vb[i] = (gn < N) ? *(const float4*)(Bm + (size_t)gn * ldb + gk)
                                 : make_float4(0.f, 0.f, 0.f, 0.f);
            } else {
                vb[i] = *(const float4*)(Bm + (size_t)gn * ldb + gk);
            }
        }
    };
    auto stsAB = [&](int buf) {
#pragma unroll
        for (int i = 0; i < 2; i++) {
            int lin = tid + i * 256;
            int r = lin >> 2, kq = lin & 3;
            float4 ta, tb;
            ta.x = __uint_as_float(f2tf32(va[i].x));
            ta.y = __uint_as_float(f2tf32(va[i].y));
            ta.z = __uint_as_float(f2tf32(va[i].z));
            ta.w = __uint_as_float(f2tf32(va[i].w));
            tb.x = __uint_as_float(f2tf32(vb[i].x));
            tb.y = __uint_as_float(f2tf32(vb[i].y));
            tb.z = __uint_as_float(f2tf32(vb[i].z));
            tb.w = __uint_as_float(f2tf32(vb[i].w));
            *(float4*)&As[buf][r * SROW + kq * 4] = ta;
            *(float4*)&Bs[buf][r * SROW + kq * 4] = tb;
        }
    };

    const int nt_tiles = K >> 4;

    ldgA(0); ldgB(0);
    stsAB(0);
    __syncthreads();

    for (int kt = 0; kt < nt_tiles; kt++) {
        const int buf = kt & 1;
        const bool has_next = (kt + 1) < nt_tiles;
        if (has_next) { ldgA((kt + 1) * 16); ldgB((kt + 1) * 16); }

        const float* As_ = As[buf];
        const float* Bs_ = Bs[buf];
#pragma unroll
        for (int k8 = 0; k8 < 2; k8++) {
            const int kc = k8 * 8;
            uint32_t af[4][4];
#pragma unroll
            for (int mt = 0; mt < 4; mt++) {
                const float* p = As_ + (wm + mt * 16 + g) * SROW + kc + l;
                af[mt][0] = __float_as_uint(p[0]);
                af[mt][1] = __float_as_uint(p[8 * SROW]);
                af[mt][2] = __float_as_uint(p[4]);
                af[mt][3] = __float_as_uint(p[8 * SROW + 4]);
            }
            uint32_t bfr[4][2];
#pragma unroll
            for (int ntile = 0; ntile < 4; ntile++) {
                const float* q = Bs_ + (wn + ntile * 8 + g) * SROW + kc + l;
                bfr[ntile][0] = __float_as_uint(q[0]);
                bfr[ntile][1] = __float_as_uint(q[4]);
            }
#pragma unroll
            for (int mt = 0; mt < 4; mt++)
#pragma unroll
                for (int ntile = 0; ntile < 4; ntile++)
                    mma_tf32(acc[mt][ntile], af[mt], bfr[ntile]);
        }

        if (has_next) {
            stsAB(buf ^ 1);
            __syncthreads();
        }
    }

    // ---- epilogue ----
    float* Cp = C;
    if (MODE == 5 || MODE == 7) Cp = C + (size_t)zi * M * ldc;

#pragma unroll
    for (int mt = 0; mt < 4; mt++) {
        const int r0l = wm + mt * 16 + g;
        const int r1l = r0l + 8;
        long gm0 = m0 + r0l, gm1 = m0 + r1l;
        bool ok0 = true, ok1 = true;
        float *crow0, *crow1;
        if (MODE == 3) {
            int a0 = sridx[r0l], a1 = sridx[r1l];
            ok0 = (a0 >= 0); ok1 = (a1 >= 0);
            crow0 = ok0 ? (Cp + (size_t)a0 * ldc) : nullptr;
            crow1 = ok1 ? (Cp + (size_t)a1 * ldc) : nullptr;
        } else {
            crow0 = Cp + (size_t)gm0 * ldc;
            crow1 = Cp + (size_t)gm1 * ldc;
        }
#pragma unroll
        for (int ntile = 0; ntile < 4; ntile++) {
            const int cn = wn + ntile * 8 + 2 * l;
            long gn = n0 + cn;
            if (MODE == 3 && gn >= N) continue;
            float2 v0 = make_float2(acc[mt][ntile][0], acc[mt][ntile][1]);
            float2 v1 = make_float2(acc[mt][ntile][2], acc[mt][ntile][3]);
            if (MODE == 0 || MODE == 3) {
                float bx = bias[gn], by = bias[gn + 1];
                if (MODE == 0 && bias2) { bx += bias2[gn]; by += bias2[gn + 1]; }
                v0.x += bx; v0.y += by; v1.x += bx; v1.y += by;
            }
            if (ok0) *(float2*)(crow0 + gn) = v0;
            if (ok1) *(float2*)(crow1 + gn) = v1;
        }
    }
}

// ---------------------------------------------------------------------------
// Support kernels
// ---------------------------------------------------------------------------
__global__ void compact_rows(const int* __restrict__ lengths,
                             int* __restrict__ rowidx, int* __restrict__ mact)
{
    __shared__ int off[BB + 1];
    __shared__ int cnts[BB];
    int b = threadIdx.x;
    int cnt = min(lengths[b] + 1, TT);
    cnts[b] = cnt;
    __syncthreads();
    if (b == 0) {
        int s = 0;
        for (int i = 0; i < BB; i++) { off[i] = s; s += cnts[i]; }
        off[BB] = s;
        *mact = s;
    }
    __syncthreads();
    int o = off[b];
    for (int j = 0; j < cnt; j++) rowidx[o + j] = b * TT + j;
}

__global__ void zero_masked(const int* __restrict__ lengths, float* __restrict__ out)
{
    int r = blockIdx.x;
    int b = r / TT, t = r % TT;
    if (lengths[b] >= t) return;
    float4 zz = make_float4(0.f, 0.f, 0.f, 0.f);
    float4* row = (float4*)(out + (size_t)r * VV);
    for (int i = threadIdx.x; i < VV / 4; i += blockDim.x) row[i] = zz;
}

__global__ void gather_kernel(const int* __restrict__ cap,
                              const float* __restrict__ emb,
                              float* __restrict__ xe)
{
    int r = blockIdx.x;
    int i = threadIdx.x;
    const float4* src = (const float4*)(emb + (size_t)cap[r] * EE);
    ((float4*)(xe + (size_t)r * EE))[i] = src[i];
}

// ---------------------------------------------------------------------------
// Fused attention, 1024 threads (32 warps) per batch row.
// a_h = b_h2a + sum of 4 hg partials (cols 4096+).
// ---------------------------------------------------------------------------
__global__ void __launch_bounds__(1024)
attn_fused(const float* __restrict__ a_feat,
           const float* __restrict__ hg,
           const float* __restrict__ b_h2a,
           const float* __restrict__ w_a,
           const float* __restrict__ b_a,
           const float* __restrict__ feature,
           float* __restrict__ z)
{
    int b = blockIdx.x;
    int tid = threadIdx.x;
    int warp = tid >> 5, lane = tid & 31;
    __shared__ __align__(16) float s_ah[DD];
    __shared__ __align__(16) float s_w[DD];
    __shared__ float s_sc[FF];
    __shared__ __align__(16) float s_zp[8][DD];
    __shared__ float red[32];
    __shared__ float bmax, bsum;

    const size_t HGS = (size_t)BB * 4608;
    for (int i = tid; i < DD / 4; i += 1024) {
        float4 v = ((const float4*)b_h2a)[i];
#pragma unroll
        for (int zp = 0; zp < 4; zp++) {
            float4 p = *(const float4*)(hg + (size_t)zp * HGS
                                        + (size_t)b * 4608 + 4096 + i * 4);
            v.x += p.x; v.y += p.y; v.z += p.z; v.w += p.w;
        }
        ((float4*)s_ah)[i] = v;
        ((float4*)s_w)[i]  = ((const float4*)w_a)[i];
    }
    __syncthreads();

    float ba = b_a[0];
    for (int f = warp; f < FF; f += 32) {
        const float4* af = (const float4*)(a_feat + ((size_t)b * FF + f) * DD);
        float s = 0.f;
#pragma unroll 4
        for (int k = lane; k < DD / 4; k += 32) {
            float4 a = af[k];
            float4 h4 = ((const float4*)s_ah)[k];
            float4 w4 = ((const float4*)s_w)[k];
            s += fmaxf(a.x + h4.x, 0.f) * w4.x
               + fmaxf(a.y + h4.y, 0.f) * w4.y
               + fmaxf(a.z + h4.z, 0.f) * w4.z
               + fmaxf(a.w + h4.w, 0.f) * w4.w;
        }
#pragma unroll
        for (int o = 16; o; o >>= 1) s += __shfl_down_sync(0xffffffffu, s, o);
        if (lane == 0) s_sc[f] = s + ba;
    }
    __syncthreads();

    // softmax over FF = 196
    float v = (tid < FF) ? s_sc[tid] : -3.0e38f;
    float m = v;
#pragma unroll
    for (int o = 16; o; o >>= 1) m = fmaxf(m, __shfl_xor_sync(0xffffffffu, m, o));
    if (lane == 0) red[warp] = m;
    __syncthreads();
    if (tid == 0) {
        float x = red[0];
        for (int w = 1; w < 32; w++) x = fmaxf(x, red[w]);
        bmax = x;
    }
    __syncthreads();
    float e = (tid < FF) ? expf(v - bmax) : 0.f;
    float s = e;
#pragma unroll
    for (int o = 16; o; o >>= 1) s += __shfl_xor_sync(0xffffffffu, s, o);
    if (lane == 0) red[warp] = s;
    __syncthreads();
    if (tid == 0) {
        float x = 0.f;
        for (int w = 0; w < 32; w++) x += red[w];
        bsum = x;
    }
    __syncthreads();
    if (tid < FF) s_sc[tid] = e / bsum;
    __syncthreads();

    // z phase: 8 subsets over f
    {
        int eighth = tid >> 7;              // 0..7
        int dt = (tid & 127) * 4;
        int f0 = (eighth * FF) >> 3;
        int f1 = ((eighth + 1) * FF) >> 3;
        const float4* fp = (const float4*)(feature + (size_t)b * FF * DD) + (dt >> 2);
        float a0 = 0.f, a1 = 0.f, a2 = 0.f, a3 = 0.f;
        for (int f = f0; f < f1; f++) {
            float4 q = fp[(size_t)f * (DD / 4)];
            float al = s_sc[f];
            a0 += al * q.x; a1 += al * q.y;
            a2 += al * q.z; a3 += al * q.w;
        }
        *(float4*)&s_zp[eighth][dt] = make_float4(a0, a1, a2, a3);
    }
    __syncthreads();
    if (tid < 128) {
        int dt = tid * 4;
        float4 u = *(const float4*)&s_zp[0][dt];
#pragma unroll
        for (int e8 = 1; e8 < 8; e8++) {
            float4 w = *(const float4*)&s_zp[e8][dt];
            u.x += w.x; u.y += w.y; u.z += w.z; u.w += w.w;
        }
        *(float4*)(z + (size_t)b * DD + dt) = u;
    }
}

__global__ void zmean_kernel(const float* __restrict__ feature,
                             float* __restrict__ z)
{
    int b = blockIdx.x;
    int d = blockIdx.y * 128 + threadIdx.x;
    const float* fp = feature + (size_t)b * FF * DD + d;
    float s0 = 0.f, s1 = 0.f, s2 = 0.f, s3 = 0.f;
    for (int f = 0; f < FF; f += 4) {
        s0 += fp[(size_t)(f + 0) * DD];
        s1 += fp[(size_t)(f + 1) * DD];
        s2 += fp[(size_t)(f + 2) * DD];
        s3 += fp[(size_t)(f + 3) * DD];
    }
    z[b * DD + d] = ((s0 + s1) + (s2 + s3)) * (1.0f / FF);
}

__device__ __forceinline__ float sigmoidf_(float x) { return 1.f / (1.f + expf(-x)); }

// LSTM pointwise, float4-vectorized (4 hh per thread):
// gates = sum(2 zg partials) + sum(4 hg partials, cols 0..4096) + gemb.
__global__ void __launch_bounds__(256)
lstm_kernel(const float* __restrict__ zg,
            const float* __restrict__ hg,
            const float* __restrict__ gemb,
            const int* __restrict__ lengths, int t,
            float* __restrict__ h, float* __restrict__ c,
            float* __restrict__ hall)
{
    int idx = blockIdx.x * blockDim.x + threadIdx.x;   // BB*HH/4 threads
    int b = idx >> 8;                                  // HH/4 = 256
    int hh = (idx & 255) * 4;
    const size_t HGS = (size_t)BB * 4608;
    const size_t ZGS = (size_t)BB * 4096;
    const float* zgb = zg + (size_t)b * 4096;
    const float* hgb = hg + (size_t)b * 4608;
    const float* ge  = gemb + ((size_t)b * TT + t) * 4 * HH;

    float4 gate[4];
#pragma unroll
    for (int g = 0; g < 4; g++) {
        int col = g * HH + hh;
        float4 v = *(const float4*)(ge + col);
        float4 q0 = *(const float4*)(zgb + col);
        float4 q1 = *(const float4*)(zgb + ZGS + col);
        v.x += q0.x + q1.x; v.y += q0.y + q1.y;
        v.z += q0.z + q1.z; v.w += q0.w + q1.w;
#pragma unroll
        for (int zp = 0; zp < 4; zp++) {
            float4 p = *(const float4*)(hgb + (size_t)zp * HGS + col);
            v.x += p.x; v.y += p.y; v.z += p.z; v.w += p.w;
        }
        gate[g] = v;
    }

    float4 cv = *(const float4*)(c + (size_t)b * HH + hh);
    float4 cn, hn;
    {
        float ii, ff, gg, oo;
        ii = sigmoidf_(gate[0].x); ff = sigmoidf_(gate[1].x);
        gg = tanhf(gate[2].x);     oo = sigmoidf_(gate[3].x);
        cn.x = ff * cv.x + ii * gg; hn.x = oo * tanhf(cn.x);
        ii = sigmoidf_(gate[0].y); ff = sigmoidf_(gate[1].y);
        gg = tanhf(gate[2].y);     oo = sigmoidf_(gate[3].y);
        cn.y = ff * cv.y + ii * gg; hn.y = oo * tanhf(cn.y);
        ii = sigmoidf_(gate[0].z); ff = sigmoidf_(gate[1].z);
        gg = tanhf(gate[2].z);     oo = sigmoidf_(gate[3].z);
        cn.z = ff * cv.z + ii * gg; hn.z = oo * tanhf(cn.z);
        ii = sigmoidf_(gate[0].w); ff = sigmoidf_(gate[1].w);
        gg = tanhf(gate[2].w);     oo = sigmoidf_(gate[3].w);
        cn.w = ff * cv.w + ii * gg; hn.w = oo * tanhf(cn.w);
    }

    *(float4*)(hall + ((size_t)b * TT + t) * HH + hh) = hn;
    if (lengths[b] >= t) {
        *(float4*)(h + (size_t)b * HH + hh) = hn;
        *(float4*)(c + (size_t)b * HH + hh) = cn;
    }
}

// ---------------------------------------------------------------------------
// Host orchestration
// ---------------------------------------------------------------------------
extern "C" void kernel_launch(void* const* d_in, const int* in_sizes, int n_in,
                              void* d_out, int out_size)
{
    const float* feature = (const float*)d_in[0];
    const int*   captions = (const int*)d_in[1];
    const int*   lengths = (const int*)d_in[2];
    const float* emb    = (const float*)d_in[3];
    const float* W_ih   = (const float*)d_in[4];
    const float* b_ih   = (const float*)d_in[5];
    const float* W_hh   = (const float*)d_in[6];
    const float* b_hh   = (const float*)d_in[7];
    const float* W_fc   = (const float*)d_in[8];
    const float* b_fc   = (const float*)d_in[9];
    const float* W_h2a  = (const float*)d_in[10];
    const float* b_h2a  = (const float*)d_in[11];
    const float* W_f2a  = (const float*)d_in[12];
    const float* b_f2a  = (const float*)d_in[13];
    const float* W_a2a  = (const float*)d_in[14];
    const float* b_a2a  = (const float*)d_in[15];
    float* out = (float*)d_out;

    float *a_feat, *x_e, *gemb, *hall, *h, *c, *z, *z0, *hg, *zg;
    int *rowidx, *mact;
    cudaGetSymbolAddress((void**)&a_feat, g_a_feat);
    cudaGetSymbolAddress((void**)&x_e,    g_x_emb);
    cudaGetSymbolAddress((void**)&gemb,   g_gemb);
    cudaGetSymbolAddress((void**)&hall,   g_hall);
    cudaGetSymbolAddress((void**)&h,      g_h);
    cudaGetSymbolAddress((void**)&c,      g_c);
    cudaGetSymbolAddress((void**)&z,      g_z);
    cudaGetSymbolAddress((void**)&z0,     g_z0);
    cudaGetSymbolAddress((void**)&hg,     g_hg);
    cudaGetSymbolAddress((void**)&zg,     g_zg);
    cudaGetSymbolAddress((void**)&rowidx, g_rowidx);
    cudaGetSymbolAddress((void**)&mact,   g_mact);

    static cudaStream_t s1 = nullptr;
    static cudaEvent_t evFork = nullptr, evA = nullptr;
    if (s1 == nullptr) {
        cudaStreamCreateWithFlags(&s1, cudaStreamNonBlocking);
        cudaEventCreateWithFlags(&evFork, cudaEventDisableTiming);
        cudaEventCreateWithFlags(&evA,    cudaEventDisableTiming);
    }

    cudaMemsetAsync(h,  0, (size_t)BB * HH * sizeof(float));
    cudaMemsetAsync(c,  0, (size_t)BB * HH * sizeof(float));
    cudaMemsetAsync(hg, 0, (size_t)4 * BB * 4608 * sizeof(float));
    gather_kernel<<<BB * TT, 128>>>(captions, emb, x_e);
    compact_rows<<<1, BB>>>(lengths, rowidx, mact);

    // Side stream: a_feat GEMM + zero_masked
    cudaEventRecord(evFork, 0);
    cudaStreamWaitEvent(s1, evFork, 0);
    mma_gemm<0><<<dim3(196, 4), 256, 0, s1>>>(
        feature, DD, W_f2a, DD, nullptr,
        b_f2a, nullptr,
        a_feat, DD, BB * FF, DD, DD, nullptr, nullptr);
    zero_masked<<<BB * TT, 256, 0, s1>>>(lengths, out);
    cudaEventRecord(evA, s1);

    // g_emb = x_emb @ W_ih[:, D:]^T + b_ih + b_hh   [2560, 512] x [4096, 512]
    mma_gemm<0><<<dim3(20, 32), 256>>>(
        x_e, EE, W_ih + DD, DD + EE, nullptr,
        b_ih, b_hh,
        gemb, 4 * HH, BB * TT, 4 * HH, EE, nullptr, nullptr);

    zmean_kernel<<<dim3(BB, DD / 128), 128>>>(feature, z0);

    for (int t = 0; t < TT; t++) {
        if (t > 0) {
            // hg = h @ [W_hh | W_h2a]^T, split-K=4 partials [4][128][4608]
            mma_gemm<7><<<dim3(1, 36, 4), 256>>>(
                h, HH, W_hh, HH, W_h2a,
                nullptr, nullptr,
                hg, 4608, BB, 4608, 256, nullptr, nullptr);

            if (t == 1) cudaStreamWaitEvent(0, evA, 0);  // a_feat ready
            attn_fused<<<BB, 1024>>>(a_feat, hg, b_h2a, W_a2a, b_a2a, feature, z);
        }

        // zg = z @ W_ih[:, :512]^T, split-K=2 partials [2][128][4096]
        mma_gemm<5><<<dim3(1, 32, 2), 256>>>(
            (t == 0) ? z0 : z, DD, W_ih, DD + EE, nullptr,
            nullptr, nullptr,
            zg, 4 * HH, BB, 4 * HH, 256, nullptr, nullptr);

        lstm_kernel<<<(BB * HH / 4) / 256, 256>>>(zg, hg, gemb, lengths, t,
                                                  h, c, hall);
    }

    // preds[active rows] = h_all @ W_fc^T + b_fc    [Mact, 1024] x [10000, 1024]
    mma_gemm<3><<<dim3(20, 79), 256>>>(
        hall, HH, W_fc, HH, nullptr,
        b_fc, nullptr,
        out, VV, BB * TT, VV, HH, rowidx, mact);
}